// round 10
// baseline (speedup 1.0000x reference)
#include <cuda_runtime.h>
#include <cuda_bf16.h>

#define L 2048
#define LMASK 2047
#define LSHIFT 11
#define PAIRMASK 0x5A48u
#define CAP 192            // finish smem-cache capacity

// ---------------- device scratch ----------------
__device__ float d_S[(size_t)L * L];          // masked symmetric matrix
__device__ unsigned long long d_best[L];      // per-vertex best edge priority (global ids)
__device__ int d_cls[L];
__device__ int d_list[2][L];                  // ping-pong active lists (global ids, ascending)
__device__ int d_nL[2];

// priority: value desc, flat index (i*L+j, i<j) asc — exact stable-sort tiebreak
__device__ __forceinline__ unsigned long long pack_g(float s, int i, int j) {
    unsigned k = (unsigned)(i * L + j);
    return ((unsigned long long)__float_as_uint(s) << 32) | (unsigned long long)(~k);
}
__device__ __forceinline__ unsigned long long warp_max(unsigned long long m) {
    #pragma unroll
    for (int o = 16; o; o >>= 1) {
        unsigned long long q = __shfl_xor_sync(0xFFFFFFFFu, m, o);
        if (q > m) m = q;
    }
    return m;
}
// triangular block map: k -> (bi, bj) with bi <= bj
__device__ __forceinline__ void tri_map(int k, int& bi, int& bj) {
    int b = (int)((__fsqrt_rn(8.0f * (float)k + 1.0f) - 1.0f) * 0.5f);
    while (b * (b + 1) / 2 > k) b--;
    while ((b + 1) * (b + 2) / 2 <= k) b++;
    bj = b;
    bi = k - b * (b + 1) / 2;
}

// ---------------- K1: classes + clear best ----------------
__global__ void kern_cls(const float* __restrict__ feat) {
    int i = blockIdx.x * blockDim.x + threadIdx.x;
    if (i >= L) return;
    float f0 = feat[(size_t)i * L];
    float f1 = feat[(size_t)L * L + (size_t)i * L];
    float f2 = feat[2 * (size_t)L * L + (size_t)i * L];
    float f3 = feat[3 * (size_t)L * L + (size_t)i * L];
    int c = 0; float m = f0;
    if (f1 > m) { m = f1; c = 1; }
    if (f2 > m) { m = f2; c = 2; }
    if (f3 > m) { m = f3; c = 3; }
    d_cls[i] = c;
    d_best[i] = 0ULL;
}

// ---------------- K2: masked symmetric S + round-1 best + zero output ----------------
__global__ void kern_build(const float* __restrict__ con, float* __restrict__ out) {
    int bi, bj; tri_map(blockIdx.x, bi, bj);      // bi <= bj

    __shared__ float sB[32][33];
    __shared__ int clsR[32], clsC[32];

    int tx = threadIdx.x, ty = threadIdx.y;
    int i = bi * 32 + ty;
    int j = bj * 32 + tx;

    if (ty == 0) { clsR[tx] = d_cls[bi * 32 + tx]; clsC[tx] = d_cls[bj * 32 + tx]; }

    float a = con[(size_t)i * L + j];
    sB[ty][tx] = con[(size_t)(bj * 32 + ty) * L + (bi * 32 + tx)];
    __syncthreads();

    float b = sB[tx][ty];          // con[j][i]
    float v = 0.5f * (a + b);
    int d = j - i;
    bool band = (d >= 4) || (d <= -4);
    bool pm = (PAIRMASK >> ((clsR[ty] << 2) | clsC[tx])) & 1u;
    float s = (band && pm) ? v : 0.0f;

    out[(size_t)i * L + j] = 0.0f;
    out[(size_t)(bj * 32 + ty) * L + (bi * 32 + tx)] = 0.0f;

    d_S[(size_t)i * L + j] = s;                   // direct tile, coalesced

    // row max (vertex i): pairs (i, j) with j > i
    unsigned long long p = (s > 0.0f && j > i) ? pack_g(s, i, j) : 0ULL;
    unsigned long long m = warp_max(p);
    if (tx == 0 && m) atomicMax(&d_best[i], m);

    // transpose s via sB reuse: mirrored S write + column best
    __syncthreads();
    sB[ty][tx] = s;
    __syncthreads();
    float s2 = sB[tx][ty];                 // value for pair (i2 = bi*32+tx, j2 = bj*32+ty)
    int i2 = bi * 32 + tx, j2 = bj * 32 + ty;
    d_S[(size_t)j2 * L + i2] = s2;                // mirrored tile, coalesced over tx
    unsigned long long p2 = (s2 > 0.0f && j2 > i2) ? pack_g(s2, i2, j2) : 0ULL;
    unsigned long long cm = warp_max(p2);
    if (tx == 0 && cm) atomicMax(&d_best[j2], cm);
}

// ---------------- K3: take (1 block; srcSel<0 = all L vertices) ----------------
__global__ void kern_take(int srcSel, int dstSel, float* __restrict__ out) {
    __shared__ int wsum[32];
    __shared__ int sTotal;
    int t = threadIdx.x;
    int lane = t & 31, wid = t >> 5;
    int n = (srcSel < 0) ? L : d_nL[srcSel];
    const int* lst = (srcSel < 0) ? 0 : d_list[srcSel];

    int f[2]; int vv[2];
    #pragma unroll
    for (int r = 0; r < 2; r++) {
        int idx = 2 * t + r;
        int fl = 0, v = -1;
        if (idx < n) {
            v = lst ? lst[idx] : idx;
            unsigned long long b = d_best[v];
            if (b) {
                unsigned k = ~((unsigned)b);
                int i = (int)(k >> LSHIFT), j = (int)(k & LMASK);
                int u = (v == i) ? j : i;
                if (d_best[u] == b) {
                    if (v == i) {   // write once per pair
                        float val = __uint_as_float((unsigned)(b >> 32));
                        out[i * L + j] = val;
                        out[j * L + i] = val;
                    }
                } else fl = 1;      // survives
            }
        }
        f[r] = fl; vv[r] = v;
    }

    int sum = f[0] + f[1];
    int x = sum;
    #pragma unroll
    for (int o = 1; o < 32; o <<= 1) { int y = __shfl_up_sync(0xFFFFFFFFu, x, o); if (lane >= o) x += y; }
    if (lane == 31) wsum[wid] = x;
    __syncthreads();
    if (wid == 0) {
        int z = wsum[lane];
        #pragma unroll
        for (int o = 1; o < 32; o <<= 1) { int y = __shfl_up_sync(0xFFFFFFFFu, z, o); if (lane >= o) z += y; }
        wsum[lane] = z;
        if (lane == 31) sTotal = z;
    }
    __syncthreads();
    int ex = (wid ? wsum[wid - 1] : 0) + x - sum;
    if (f[0]) d_list[dstSel][ex] = vv[0];
    if (f[1]) d_list[dstSel][ex + f[0]] = vv[1];
    if (t == 0) d_nL[dstSel] = sTotal;
}

// ---------------- K4: best over active set — coalesced full-row scan + alive mask ----------------
// Row v: read S[v][0..L) as float4 (16 vector loads/lane -> high MLP, coalesced),
// filter by smem alive flag. Bit-identical priorities vs the gathered version.
__global__ void kern_bestG(int sel) {
    __shared__ unsigned char sAlive[L];
    __shared__ int sAct[L];
    int n = d_nL[sel];
    if (n == 0) return;
    const int* lst = d_list[sel];
    for (int t = threadIdx.x; t < L; t += blockDim.x) sAlive[t] = 0;
    __syncthreads();
    for (int t = threadIdx.x; t < n; t += blockDim.x) {
        int v = lst[t];
        sAct[t] = v;
        sAlive[v] = 1;
    }
    __syncthreads();

    int lane = threadIdx.x & 31;
    int wid = threadIdx.x >> 5;                       // 0..7
    int start = blockIdx.x * 8 + wid;                 // rows interleaved over blocks
    int stride = gridDim.x * 8;

    for (int a = start; a < n; a += stride) {
        int v = sAct[a];
        const float4* __restrict__ row = (const float4*)(d_S + (size_t)v * L);
        unsigned long long m = 0ULL;
        #pragma unroll 4
        for (int q = lane; q < L / 4; q += 32) {
            float4 fv = row[q];
            int u = q * 4;
            if (fv.x > 0.0f && sAlive[u]) {
                unsigned long long p = (v < u) ? pack_g(fv.x, v, u) : pack_g(fv.x, u, v);
                if (p > m) m = p;
            }
            if (fv.y > 0.0f && sAlive[u + 1]) {
                unsigned long long p = (v < u + 1) ? pack_g(fv.y, v, u + 1) : pack_g(fv.y, u + 1, v);
                if (p > m) m = p;
            }
            if (fv.z > 0.0f && sAlive[u + 2]) {
                unsigned long long p = (v < u + 2) ? pack_g(fv.z, v, u + 2) : pack_g(fv.z, u + 2, v);
                if (p > m) m = p;
            }
            if (fv.w > 0.0f && sAlive[u + 3]) {
                unsigned long long p = (v < u + 3) ? pack_g(fv.w, v, u + 3) : pack_g(fv.w, u + 3, v);
                if (p > m) m = p;
            }
        }
        m = warp_max(m);
        if (lane == 0) d_best[v] = m;
    }
}

// ---------------- K5: persistent tail with smem-cached S submatrix ----------------
__global__ void kern_finish(int sel, float* __restrict__ out) {
    extern __shared__ float sC[];              // CAP*CAP floats (dynamic)
    __shared__ int sCur[L];
    __shared__ int sTmp[L];
    __shared__ short sPos[L];
    __shared__ unsigned long long sBest[L];
    __shared__ int wsum[32];
    __shared__ int sTotal;

    int t = threadIdx.x, lane = t & 31, wid = t >> 5;
    int n = d_nL[sel];
    if (n == 0) return;

    for (int x = t; x < n; x += 1024) {
        int v = d_list[sel][x];
        sCur[x] = v;
        sPos[v] = (short)x;
        sBest[v] = d_best[v];
    }
    __syncthreads();

    bool useC = (n <= CAP);
    int ne = n;
    if (useC) {
        for (int idx = t; idx < ne * ne; idx += 1024) {
            int ai = idx / ne, bi2 = idx - ai * ne;
            sC[idx] = d_S[(size_t)sCur[ai] * L + sCur[bi2]];
        }
        __syncthreads();
    }

    while (n > 0) {
        // ---- take ----
        int f[2]; int vv[2];
        #pragma unroll
        for (int r = 0; r < 2; r++) {
            int idx = 2 * t + r;
            int fl = 0, v = -1;
            if (idx < n) {
                v = sCur[idx];
                unsigned long long b = sBest[v];
                if (b) {
                    unsigned k = ~((unsigned)b);
                    int i = (int)(k >> LSHIFT), j = (int)(k & LMASK);
                    int u = (v == i) ? j : i;
                    if (sBest[u] == b) {
                        if (v == i) {
                            float val = __uint_as_float((unsigned)(b >> 32));
                            out[i * L + j] = val;
                            out[j * L + i] = val;
                        }
                    } else fl = 1;
                }
            }
            f[r] = fl; vv[r] = v;
        }

        int sum = f[0] + f[1];
        int x = sum;
        #pragma unroll
        for (int o = 1; o < 32; o <<= 1) { int y = __shfl_up_sync(0xFFFFFFFFu, x, o); if (lane >= o) x += y; }
        if (lane == 31) wsum[wid] = x;
        __syncthreads();
        if (wid == 0) {
            int z = wsum[lane];
            #pragma unroll
            for (int o = 1; o < 32; o <<= 1) { int y = __shfl_up_sync(0xFFFFFFFFu, z, o); if (lane >= o) z += y; }
            wsum[lane] = z;
            if (lane == 31) sTotal = z;
        }
        __syncthreads();
        int ex = (wid ? wsum[wid - 1] : 0) + x - sum;
        if (f[0]) sTmp[ex] = vv[0];
        if (f[1]) sTmp[ex + f[0]] = vv[1];
        __syncthreads();
        int nn = sTotal;
        for (int x2 = t; x2 < nn; x2 += 1024) sCur[x2] = sTmp[x2];
        __syncthreads();
        n = nn;
        if (n == 0) break;

        // ---- best ----
        for (int ai = wid; ai < n; ai += 32) {
            int v = sCur[ai];
            int pa = useC ? sPos[v] : 0;
            unsigned long long m = 0ULL;
            for (int li = lane; li < n; li += 32) {
                int u = sCur[li];
                float s = useC ? sC[pa * ne + sPos[u]]
                               : d_S[(size_t)v * L + u];
                if (s > 0.0f) {
                    unsigned long long p = (v < u) ? pack_g(s, v, u) : pack_g(s, u, v);
                    if (p > m) m = p;
                }
            }
            m = warp_max(m);
            if (lane == 0) sBest[v] = m;
        }
        __syncthreads();
    }
}

// ---------------- launch ----------------
extern "C" void kernel_launch(void* const* d_in, const int* in_sizes, int n_in,
                              void* d_out, int out_size) {
    const float* con  = (const float*)d_in[0];
    const float* feat = (const float*)d_in[1];
    if (n_in >= 2 && in_sizes[0] > in_sizes[1]) {
        const float* tmp = con; con = feat; feat = tmp;
    }
    float* out = (float*)d_out;

    static int smemSet = 0;
    if (!smemSet) {
        cudaFuncSetAttribute(kern_finish, cudaFuncAttributeMaxDynamicSharedMemorySize,
                             CAP * CAP * (int)sizeof(float));
        smemSet = 1;
    }

    const int TRI32 = (L / 32) * (L / 32 + 1) / 2;   // 2080
    dim3 tb(32, 32);

    kern_cls<<<8, 256>>>(feat);
    kern_build<<<TRI32, tb>>>(con, out);           // S + round-1 best + output zeroing

    kern_take<<<1, 1024>>>(-1, 0, out);            // take1 -> list0
    kern_bestG<<<148, 256>>>(0);                   // best2
    kern_take<<<1, 1024>>>(0, 1, out);             // take2
    kern_bestG<<<148, 256>>>(1);                   // best3
    kern_take<<<1, 1024>>>(1, 0, out);             // take3
    kern_bestG<<<148, 256>>>(0);                   // best4
    kern_take<<<1, 1024>>>(0, 1, out);             // take4
    kern_bestG<<<148, 256>>>(1);                   // best5
    kern_take<<<1, 1024>>>(1, 0, out);             // take5
    kern_bestG<<<148, 256>>>(0);                   // best6

    kern_finish<<<1, 1024, CAP * CAP * (int)sizeof(float)>>>(0, out);  // tail (n small)
}

// round 11
// speedup vs baseline: 1.2926x; 1.2926x over previous
#include <cuda_runtime.h>
#include <cuda_bf16.h>

#define L 2048
#define LMASK 2047
#define LSHIFT 11
#define PAIRMASK 0x5A48u
#define CAP 192            // finish smem-cache capacity

// ---------------- device scratch ----------------
__device__ float d_S[(size_t)L * L];          // masked symmetric matrix
__device__ unsigned long long d_best[L];      // per-vertex best edge priority (cached, lazy)
__device__ int d_cls[L];
__device__ int d_list[2][L];                  // ping-pong survivor lists (global ids, ascending)
__device__ int d_nL[2];
__device__ int d_resc[L];                     // rescan subset of survivors
__device__ int d_nResc;

// priority: value desc, flat index (i*L+j, i<j) asc — exact stable-sort tiebreak
__device__ __forceinline__ unsigned long long pack_g(float s, int i, int j) {
    unsigned k = (unsigned)(i * L + j);
    return ((unsigned long long)__float_as_uint(s) << 32) | (unsigned long long)(~k);
}
__device__ __forceinline__ unsigned long long warp_max(unsigned long long m) {
    #pragma unroll
    for (int o = 16; o; o >>= 1) {
        unsigned long long q = __shfl_xor_sync(0xFFFFFFFFu, m, o);
        if (q > m) m = q;
    }
    return m;
}
// triangular block map: k -> (bi, bj) with bi <= bj
__device__ __forceinline__ void tri_map(int k, int& bi, int& bj) {
    int b = (int)((__fsqrt_rn(8.0f * (float)k + 1.0f) - 1.0f) * 0.5f);
    while (b * (b + 1) / 2 > k) b--;
    while ((b + 1) * (b + 2) / 2 <= k) b++;
    bj = b;
    bi = k - b * (b + 1) / 2;
}

// ---------------- K1: classes + clear best ----------------
__global__ void kern_cls(const float* __restrict__ feat) {
    int i = blockIdx.x * blockDim.x + threadIdx.x;
    if (i >= L) return;
    float f0 = feat[(size_t)i * L];
    float f1 = feat[(size_t)L * L + (size_t)i * L];
    float f2 = feat[2 * (size_t)L * L + (size_t)i * L];
    float f3 = feat[3 * (size_t)L * L + (size_t)i * L];
    int c = 0; float m = f0;
    if (f1 > m) { m = f1; c = 1; }
    if (f2 > m) { m = f2; c = 2; }
    if (f3 > m) { m = f3; c = 3; }
    d_cls[i] = c;
    d_best[i] = 0ULL;                       // must re-zero every replay (take no longer clears)
}

// ---------------- K2: masked symmetric S + round-1 best + zero output ----------------
__global__ void kern_build(const float* __restrict__ con, float* __restrict__ out) {
    int bi, bj; tri_map(blockIdx.x, bi, bj);      // bi <= bj

    __shared__ float sB[32][33];
    __shared__ int clsR[32], clsC[32];

    int tx = threadIdx.x, ty = threadIdx.y;
    int i = bi * 32 + ty;
    int j = bj * 32 + tx;

    if (ty == 0) { clsR[tx] = d_cls[bi * 32 + tx]; clsC[tx] = d_cls[bj * 32 + tx]; }

    float a = con[(size_t)i * L + j];
    sB[ty][tx] = con[(size_t)(bj * 32 + ty) * L + (bi * 32 + tx)];
    __syncthreads();

    float b = sB[tx][ty];          // con[j][i]
    float v = 0.5f * (a + b);
    int d = j - i;
    bool band = (d >= 4) || (d <= -4);
    bool pm = (PAIRMASK >> ((clsR[ty] << 2) | clsC[tx])) & 1u;
    float s = (band && pm) ? v : 0.0f;

    out[(size_t)i * L + j] = 0.0f;
    out[(size_t)(bj * 32 + ty) * L + (bi * 32 + tx)] = 0.0f;

    d_S[(size_t)i * L + j] = s;                   // direct tile, coalesced

    // row max (vertex i): pairs (i, j) with j > i
    unsigned long long p = (s > 0.0f && j > i) ? pack_g(s, i, j) : 0ULL;
    unsigned long long m = warp_max(p);
    if (tx == 0 && m) atomicMax(&d_best[i], m);

    // transpose s via sB reuse: mirrored S write + column best
    __syncthreads();
    sB[ty][tx] = s;
    __syncthreads();
    float s2 = sB[tx][ty];                 // value for pair (i2 = bi*32+tx, j2 = bj*32+ty)
    int i2 = bi * 32 + tx, j2 = bj * 32 + ty;
    d_S[(size_t)j2 * L + i2] = s2;                // mirrored tile, coalesced over tx
    unsigned long long p2 = (s2 > 0.0f && j2 > i2) ? pack_g(s2, i2, j2) : 0ULL;
    unsigned long long cm = warp_max(p2);
    if (tx == 0 && cm) atomicMax(&d_best[j2], cm);
}

// ---------------- K3: take + classify (1 block; srcSel<0 = all L vertices) ----------------
// Emits: survivor list (dstSel) AND rescan subset (survivors whose best partner was taken).
__global__ void kern_take(int srcSel, int dstSel, float* __restrict__ out) {
    __shared__ int wsum[32];
    __shared__ int sTotal;
    int t = threadIdx.x;
    int lane = t & 31, wid = t >> 5;
    int n = (srcSel < 0) ? L : d_nL[srcSel];
    const int* lst = (srcSel < 0) ? 0 : d_list[srcSel];

    int f[2];   // 0=dead/taken, 1=survive cached, 2=survive rescan
    int vv[2];
    #pragma unroll
    for (int r = 0; r < 2; r++) {
        int idx = 2 * t + r;
        int fl = 0, v = -1;
        if (idx < n) {
            v = lst ? lst[idx] : idx;
            unsigned long long b = d_best[v];
            if (b) {
                unsigned k = ~((unsigned)b);
                int i = (int)(k >> LSHIFT), j = (int)(k & LMASK);
                int u = (v == i) ? j : i;
                unsigned long long bu = d_best[u];
                if (bu == b) {
                    if (v == i) {   // taken: write once per pair
                        float val = __uint_as_float((unsigned)(b >> 32));
                        out[i * L + j] = val;
                        out[j * L + i] = val;
                    }
                } else {
                    // v survives; was u taken this round? (u's best is mutual)
                    unsigned k2 = ~((unsigned)bu);
                    int i2 = (int)(k2 >> LSHIFT), j2 = (int)(k2 & LMASK);
                    int w = (u == i2) ? j2 : i2;
                    int u_taken = (d_best[w] == bu);
                    fl = u_taken ? 2 : 1;
                }
            }
        }
        f[r] = fl; vv[r] = v;
    }

    // ---- scan 1: survivors (fl >= 1) -> d_list[dstSel] ----
    {
        int g0 = (f[0] >= 1), g1 = (f[1] >= 1);
        int sum = g0 + g1;
        int x = sum;
        #pragma unroll
        for (int o = 1; o < 32; o <<= 1) { int y = __shfl_up_sync(0xFFFFFFFFu, x, o); if (lane >= o) x += y; }
        if (lane == 31) wsum[wid] = x;
        __syncthreads();
        if (wid == 0) {
            int z = wsum[lane];
            #pragma unroll
            for (int o = 1; o < 32; o <<= 1) { int y = __shfl_up_sync(0xFFFFFFFFu, z, o); if (lane >= o) z += y; }
            wsum[lane] = z;
            if (lane == 31) sTotal = z;
        }
        __syncthreads();
        int ex = (wid ? wsum[wid - 1] : 0) + x - sum;
        if (g0) d_list[dstSel][ex] = vv[0];
        if (g1) d_list[dstSel][ex + g0] = vv[1];
        if (t == 0) d_nL[dstSel] = sTotal;
    }
    __syncthreads();

    // ---- scan 2: rescan subset (fl == 2) -> d_resc ----
    {
        int g0 = (f[0] == 2), g1 = (f[1] == 2);
        int sum = g0 + g1;
        int x = sum;
        #pragma unroll
        for (int o = 1; o < 32; o <<= 1) { int y = __shfl_up_sync(0xFFFFFFFFu, x, o); if (lane >= o) x += y; }
        if (lane == 31) wsum[wid] = x;
        __syncthreads();
        if (wid == 0) {
            int z = wsum[lane];
            #pragma unroll
            for (int o = 1; o < 32; o <<= 1) { int y = __shfl_up_sync(0xFFFFFFFFu, z, o); if (lane >= o) z += y; }
            wsum[lane] = z;
            if (lane == 31) sTotal = z;
        }
        __syncthreads();
        int ex = (wid ? wsum[wid - 1] : 0) + x - sum;
        if (g0) d_resc[ex] = vv[0];
        if (g1) d_resc[ex + g0] = vv[1];
        if (t == 0) d_nResc = sTotal;
    }
}

// ---------------- K4: best — rescan only flagged rows, gathered over survivor list ----------------
__global__ void kern_bestG(int sel) {
    __shared__ int sAct[L];
    int n = d_nL[sel];
    int m0 = d_nResc;
    if (m0 == 0) return;
    const int* lst = d_list[sel];
    for (int t = threadIdx.x; t < n; t += blockDim.x) sAct[t] = lst[t];
    __syncthreads();

    int lane = threadIdx.x & 31;
    int wid = threadIdx.x >> 5;                       // 0..7
    int start = blockIdx.x * 8 + wid;                 // rows interleaved over blocks
    int stride = gridDim.x * 8;

    for (int a = start; a < m0; a += stride) {
        int v = d_resc[a];
        const float* __restrict__ row = d_S + (size_t)v * L;
        unsigned long long m = 0ULL;
        for (int l = lane; l < n; l += 32) {
            int u = sAct[l];
            float s = row[u];
            if (s > 0.0f) {
                unsigned long long p = (v < u) ? pack_g(s, v, u) : pack_g(s, u, v);
                if (p > m) m = p;
            }
        }
        m = warp_max(m);
        if (lane == 0) d_best[v] = m;
    }
}

// ---------------- K5: persistent tail with smem-cached S submatrix ----------------
__global__ void kern_finish(int sel, float* __restrict__ out) {
    extern __shared__ float sC[];              // CAP*CAP floats (dynamic)
    __shared__ int sCur[L];
    __shared__ int sTmp[L];
    __shared__ short sPos[L];
    __shared__ unsigned long long sBest[L];
    __shared__ int wsum[32];
    __shared__ int sTotal;

    int t = threadIdx.x, lane = t & 31, wid = t >> 5;
    int n = d_nL[sel];
    if (n == 0) return;

    for (int x = t; x < n; x += 1024) {
        int v = d_list[sel][x];
        sCur[x] = v;
        sPos[v] = (short)x;
        sBest[v] = d_best[v];
    }
    __syncthreads();

    bool useC = (n <= CAP);
    int ne = n;
    if (useC) {
        for (int idx = t; idx < ne * ne; idx += 1024) {
            int ai = idx / ne, bi2 = idx - ai * ne;
            sC[idx] = d_S[(size_t)sCur[ai] * L + sCur[bi2]];
        }
        __syncthreads();
    }

    while (n > 0) {
        // ---- take ----
        int f[2]; int vv[2];
        #pragma unroll
        for (int r = 0; r < 2; r++) {
            int idx = 2 * t + r;
            int fl = 0, v = -1;
            if (idx < n) {
                v = sCur[idx];
                unsigned long long b = sBest[v];
                if (b) {
                    unsigned k = ~((unsigned)b);
                    int i = (int)(k >> LSHIFT), j = (int)(k & LMASK);
                    int u = (v == i) ? j : i;
                    if (sBest[u] == b) {
                        if (v == i) {
                            float val = __uint_as_float((unsigned)(b >> 32));
                            out[i * L + j] = val;
                            out[j * L + i] = val;
                        }
                    } else fl = 1;
                }
            }
            f[r] = fl; vv[r] = v;
        }

        int sum = f[0] + f[1];
        int x = sum;
        #pragma unroll
        for (int o = 1; o < 32; o <<= 1) { int y = __shfl_up_sync(0xFFFFFFFFu, x, o); if (lane >= o) x += y; }
        if (lane == 31) wsum[wid] = x;
        __syncthreads();
        if (wid == 0) {
            int z = wsum[lane];
            #pragma unroll
            for (int o = 1; o < 32; o <<= 1) { int y = __shfl_up_sync(0xFFFFFFFFu, z, o); if (lane >= o) z += y; }
            wsum[lane] = z;
            if (lane == 31) sTotal = z;
        }
        __syncthreads();
        int ex = (wid ? wsum[wid - 1] : 0) + x - sum;
        if (f[0]) sTmp[ex] = vv[0];
        if (f[1]) sTmp[ex + f[0]] = vv[1];
        __syncthreads();
        int nn = sTotal;
        for (int x2 = t; x2 < nn; x2 += 1024) sCur[x2] = sTmp[x2];
        __syncthreads();
        n = nn;
        if (n == 0) break;

        // ---- best ----
        for (int ai = wid; ai < n; ai += 32) {
            int v = sCur[ai];
            int pa = useC ? sPos[v] : 0;
            unsigned long long m = 0ULL;
            for (int li = lane; li < n; li += 32) {
                int u = sCur[li];
                float s = useC ? sC[pa * ne + sPos[u]]
                               : d_S[(size_t)v * L + u];
                if (s > 0.0f) {
                    unsigned long long p = (v < u) ? pack_g(s, v, u) : pack_g(s, u, v);
                    if (p > m) m = p;
                }
            }
            m = warp_max(m);
            if (lane == 0) sBest[v] = m;
        }
        __syncthreads();
    }
}

// ---------------- launch ----------------
extern "C" void kernel_launch(void* const* d_in, const int* in_sizes, int n_in,
                              void* d_out, int out_size) {
    const float* con  = (const float*)d_in[0];
    const float* feat = (const float*)d_in[1];
    if (n_in >= 2 && in_sizes[0] > in_sizes[1]) {
        const float* tmp = con; con = feat; feat = tmp;
    }
    float* out = (float*)d_out;

    static int smemSet = 0;
    if (!smemSet) {
        cudaFuncSetAttribute(kern_finish, cudaFuncAttributeMaxDynamicSharedMemorySize,
                             CAP * CAP * (int)sizeof(float));
        smemSet = 1;
    }

    const int TRI32 = (L / 32) * (L / 32 + 1) / 2;   // 2080
    dim3 tb(32, 32);

    kern_cls<<<8, 256>>>(feat);
    kern_build<<<TRI32, tb>>>(con, out);           // S + round-1 best + output zeroing

    kern_take<<<1, 1024>>>(-1, 0, out);            // take1 -> list0 + rescan set
    kern_bestG<<<128, 256>>>(0);                   // best2 (rescan rows only)
    kern_take<<<1, 1024>>>(0, 1, out);             // take2
    kern_bestG<<<128, 256>>>(1);                   // best3
    kern_take<<<1, 1024>>>(1, 0, out);             // take3
    kern_bestG<<<128, 256>>>(0);                   // best4
    kern_take<<<1, 1024>>>(0, 1, out);             // take4
    kern_bestG<<<128, 256>>>(1);                   // best5
    kern_take<<<1, 1024>>>(1, 0, out);             // take5
    kern_bestG<<<128, 256>>>(0);                   // best6

    kern_finish<<<1, 1024, CAP * CAP * (int)sizeof(float)>>>(0, out);  // tail (n ~130)
}